// round 4
// baseline (speedup 1.0000x reference)
#include <cuda_runtime.h>

// MinArchitecture scan, 4 independent rows per thread (ILP interleave):
//   diff = h - x_t; t = tanh(d0*diff)
//   yh = c0 + c1*t + c2*t^2   (pre-halved: sigmoid(y) = 0.5 + 0.5*tanh(y/2))
//   s = 0.5 + 0.5*tanh(yh);   h = x_t + s*diff

#define SEQ   512
#define IL    4          // rows per thread
#define BLOCK 32
#define CHUNK 16         // floats per chunk per row (4 x float4)

__device__ __forceinline__ float tanh_fast(float x) {
    float y;
    asm("tanh.approx.f32 %0, %1;" : "=f"(y) : "f"(x));
    return y;
}

__global__ void __launch_bounds__(BLOCK) rnn_scan_kernel(
    const float* __restrict__ X,
    const float* __restrict__ W1,
    const float* __restrict__ W2,
    const float* __restrict__ bias,
    const float* __restrict__ Wz,
    const float* __restrict__ Ws,
    float* __restrict__ out)
{
    const int t0 = blockIdx.x * BLOCK + threadIdx.x;
    const size_t r0 = (size_t)t0 * IL;

    // ----- uniform scalar constants -----
    const float a1 = 1.0f / (1.0f + expf(W1[1] - W1[0]));
    const float a2 = 1.0f / (1.0f + expf(W2[1] - W2[0]));
    const float d0 = a1 - a2;
    const float wz = Wz[0];
    const float ws = Ws[0];
    const float b  = bias[0];
    const float c0 = 0.5f * (b + wz);
    const float c1 = 0.5f * ws;
    const float c2 = -wz;

    const float4* px[IL];
    #pragma unroll
    for (int i = 0; i < IL; ++i)
        px[i] = reinterpret_cast<const float4*>(X + (r0 + i) * SEQ);

    float A[IL][CHUNK], B[IL][CHUNK];
    float h[IL];

    // load chunk 0 -> A, chunk 1 -> B
    #pragma unroll
    for (int i = 0; i < IL; ++i)
        #pragma unroll
        for (int j = 0; j < 4; ++j)
            *reinterpret_cast<float4*>(&A[i][4 * j]) = px[i][j];
    #pragma unroll
    for (int i = 0; i < IL; ++i)
        #pragma unroll
        for (int j = 0; j < 4; ++j)
            *reinterpret_cast<float4*>(&B[i][4 * j]) = px[i][4 + j];

    #pragma unroll
    for (int i = 0; i < IL; ++i) h[i] = A[i][0];   // h0 = X[:, 0]

#define STEP(i, XT) do {                                      \
        float diff = h[i] - (XT);                             \
        float tt   = tanh_fast(d0 * diff);                    \
        float yh   = fmaf(fmaf(c2, tt, c1), tt, c0);          \
        float s    = fmaf(0.5f, tanh_fast(yh), 0.5f);         \
        h[i]       = fmaf(s, diff, (XT));                     \
    } while (0)

#define RUN_CHUNK(V, E0) do {                                 \
        _Pragma("unroll")                                     \
        for (int e = (E0); e < CHUNK; ++e) {                  \
            _Pragma("unroll")                                 \
            for (int i = 0; i < IL; ++i) STEP(i, (V)[i][e]);  \
        }                                                     \
    } while (0)

    // chunk 0 (skip element 0 = h0)
    RUN_CHUNK(A, 1);

    // chunks 1..31; B holds chunk 1
    #pragma unroll 1
    for (int c = 2; c < SEQ / CHUNK; c += 2) {
        // prefetch chunk c into A
        #pragma unroll
        for (int i = 0; i < IL; ++i)
            #pragma unroll
            for (int j = 0; j < 4; ++j)
                *reinterpret_cast<float4*>(&A[i][4 * j]) = px[i][c * 4 + j];

        RUN_CHUNK(B, 0);          // process chunk c-1

        // prefetch chunk c+1 into B (c max = 30 -> chunk 31, in bounds)
        #pragma unroll
        for (int i = 0; i < IL; ++i)
            #pragma unroll
            for (int j = 0; j < 4; ++j)
                *reinterpret_cast<float4*>(&B[i][4 * j]) = px[i][(c + 1) * 4 + j];

        RUN_CHUNK(A, 0);          // process chunk c
    }

    RUN_CHUNK(B, 0);              // final chunk 31

    // 4 consecutive outputs per thread, r0 is 4-aligned -> float4 store
    float4 o;
    o.x = h[0]; o.y = h[1]; o.z = h[2]; o.w = h[3];
    *reinterpret_cast<float4*>(out + r0) = o;
}

extern "C" void kernel_launch(void* const* d_in, const int* in_sizes, int n_in,
                              void* d_out, int out_size)
{
    const float* X    = (const float*)d_in[0];
    const float* W1   = (const float*)d_in[1];
    const float* W2   = (const float*)d_in[2];
    const float* bias = (const float*)d_in[3];
    const float* Wz   = (const float*)d_in[4];
    const float* Ws   = (const float*)d_in[5];
    float* out = (float*)d_out;

    const int batch = out_size;                        // 65536
    const int grid  = (batch + IL * BLOCK - 1) / (IL * BLOCK);   // 512
    rnn_scan_kernel<<<grid, BLOCK>>>(X, W1, W2, bias, Wz, Ws, out);
}

// round 5
// speedup vs baseline: 1.0831x; 1.0831x over previous
#include <cuda_runtime.h>
#include <cuda_fp16.h>

// MinArchitecture scan, 2 rows per thread packed into f16x2 tanh lanes.
// Recurrence (exact algebra):
//   diff_1 = x0 - x1
//   for t=1..510: s_t = G(diff_t);  diff_{t+1} = (x_t - x_{t+1}) + s_t*diff_t
//   out = x_511 + G(diff_511)*diff_511
// G(d) = sigmoid(b + ws*tanh(d0*d) + wz*(1-2*tanh^2(d0*d)))
//      = 0.5 + 0.5*tanh(c0 + c1*t + c2*t^2),  t = tanh(d0*d)
// Middle section in f16x2 (tanh.approx.f16x2 + HFMA2), diff stays f32.

#define SEQ   512
#define BLOCK 64

__device__ __forceinline__ unsigned htanh2u(unsigned x) {
    unsigned y;
    asm("tanh.approx.f16x2 %0, %1;" : "=r"(y) : "r"(x));
    return y;
}
__device__ __forceinline__ unsigned hfma2u(unsigned a, unsigned b, unsigned c) {
    unsigned r;
    asm("fma.rn.f16x2 %0, %1, %2, %3;" : "=r"(r) : "r"(a), "r"(b), "r"(c));
    return r;
}
// pack two f32 -> f16x2 (lo = first arg, hi = second arg)
__device__ __forceinline__ unsigned f2h2(float lo, float hi) {
    unsigned r;
    asm("cvt.rn.f16x2.f32 %0, %2, %1;" : "=r"(r) : "f"(lo), "f"(hi));
    return r;
}

// f16 (positive, <=1.0) -> f32 bit trick: mantissa/exp shift + rebias.
// For s in [0,1]: exact for normal f16; denormal f16 (s < 6.1e-5) maps to a
// value <= 6e-5 (abs err <= 6e-5, harmless since s ~ 0 there).
#define H2F_LO(u) __uint_as_float((((u) << 13) & 0x0FFFE000u) | 0x38000000u)
#define H2F_HI(u) __uint_as_float((((u) >> 3)  & 0x0FFFE000u) | 0x38000000u)

__global__ void __launch_bounds__(BLOCK, 1) rnn_scan_kernel(
    const float* __restrict__ X,
    const float* __restrict__ W1,
    const float* __restrict__ W2,
    const float* __restrict__ bias,
    const float* __restrict__ Wz,
    const float* __restrict__ Ws,
    float* __restrict__ out)
{
    const int tid = blockIdx.x * BLOCK + threadIdx.x;
    const size_t r0 = (size_t)tid * 2;

    // ----- uniform scalar constants -----
    const float a1 = 1.0f / (1.0f + expf(W1[1] - W1[0]));
    const float a2 = 1.0f / (1.0f + expf(W2[1] - W2[0]));
    const float d0 = a1 - a2;
    const float wz = Wz[0];
    const float ws = Ws[0];
    const float b  = bias[0];
    const float c0 = 0.5f * (b + wz);
    const float c1 = 0.5f * ws;
    const float c2 = -wz;

    const unsigned c0h = f2h2(c0, c0);
    const unsigned c1h = f2h2(c1, c1);
    const unsigned c2h = f2h2(c2, c2);
    const unsigned h05 = f2h2(0.5f, 0.5f);

    const float4* pxa = reinterpret_cast<const float4*>(X + r0 * SEQ);
    const float4* pxb = reinterpret_cast<const float4*>(X + (r0 + 1) * SEQ);

    float A0[16], A1[16], B0[16], B1[16];

#define LOADC(D0, D1, c) do {                                          \
        _Pragma("unroll")                                              \
        for (int j = 0; j < 4; ++j) {                                  \
            *reinterpret_cast<float4*>(&(D0)[4 * j]) = pxa[(c) * 4 + j]; \
            *reinterpret_cast<float4*>(&(D1)[4 * j]) = pxb[(c) * 4 + j]; \
        }                                                              \
    } while (0)

    float da, db;

    // one packed recurrence step: s = G(diff) in f16x2, diff' = dx + s*diff
#define STEP(DXA, DXB) do {                                            \
        unsigned uh = f2h2(d0 * da, d0 * db);                          \
        unsigned t2 = htanh2u(uh);                                     \
        unsigned y2 = hfma2u(t2, hfma2u(t2, c2h, c1h), c0h);           \
        unsigned w2 = htanh2u(y2);                                     \
        unsigned s2 = hfma2u(w2, h05, h05);                            \
        float sa = H2F_LO(s2);                                         \
        float sb = H2F_HI(s2);                                         \
        da = fmaf(sa, da, (DXA));                                      \
        db = fmaf(sb, db, (DXB));                                      \
    } while (0)

    // 16 steps over a full chunk; (na, nb) = first element of NEXT chunk
#define PROC16(Xa, Xb, na, nb) do {                                    \
        _Pragma("unroll")                                              \
        for (int e = 0; e < 15; ++e)                                   \
            STEP((Xa)[e] - (Xa)[e + 1], (Xb)[e] - (Xb)[e + 1]);        \
        STEP((Xa)[15] - (na), (Xb)[15] - (nb));                        \
    } while (0)

    LOADC(A0, A1, 0);
    LOADC(B0, B1, 1);

    // init: diff_1 = x0 - x1
    da = A0[0] - A0[1];
    db = A1[0] - A1[1];

    // chunk 0: steps t = 1..15 (local e = 1..14 + seam)
    #pragma unroll
    for (int e = 1; e < 15; ++e)
        STEP(A0[e] - A0[e + 1], A1[e] - A1[e + 1]);
    STEP(A0[15] - B0[0], A1[15] - B1[0]);

    // chunks 1..30, R3-style rolling double buffer
    #pragma unroll 1
    for (int c = 2; c < SEQ / 16; c += 2) {
        LOADC(A0, A1, c);                    // prefetch chunk c
        PROC16(B0, B1, A0[0], A1[0]);        // process chunk c-1
        LOADC(B0, B1, c + 1);                // prefetch chunk c+1 (max 31)
        PROC16(A0, A1, B0[0], B1[0]);        // process chunk c
    }

    // chunk 31: 15 normal steps (t = 496..510) + final output step t = 511
    #pragma unroll
    for (int e = 0; e < 15; ++e)
        STEP(B0[e] - B0[e + 1], B1[e] - B1[e + 1]);

    // final: s_511 from diff_511; h = x_511 + s*diff
    {
        unsigned uh = f2h2(d0 * da, d0 * db);
        unsigned t2 = htanh2u(uh);
        unsigned y2 = hfma2u(t2, hfma2u(t2, c2h, c1h), c0h);
        unsigned w2 = htanh2u(y2);
        unsigned s2 = hfma2u(w2, h05, h05);
        float sa = H2F_LO(s2);
        float sb = H2F_HI(s2);
        float2 o;
        o.x = fmaf(sa, da, B0[15]);
        o.y = fmaf(sb, db, B1[15]);
        *reinterpret_cast<float2*>(out + r0) = o;
    }
}

extern "C" void kernel_launch(void* const* d_in, const int* in_sizes, int n_in,
                              void* d_out, int out_size)
{
    const float* X    = (const float*)d_in[0];
    const float* W1   = (const float*)d_in[1];
    const float* W2   = (const float*)d_in[2];
    const float* bias = (const float*)d_in[3];
    const float* Wz   = (const float*)d_in[4];
    const float* Ws   = (const float*)d_in[5];
    float* out = (float*)d_out;

    const int batch = out_size;                          // 65536
    const int grid  = (batch + 2 * BLOCK - 1) / (2 * BLOCK);  // 512
    rnn_scan_kernel<<<grid, BLOCK>>>(X, W1, W2, bias, Wz, Ws, out);
}

// round 7
// speedup vs baseline: 1.3111x; 1.2105x over previous
#include <cuda_runtime.h>
#include <cstdint>

// MinArchitecture scan, 1 row/thread, f32 math, cp.async smem pipeline.
//   diff = h - x_t; t = tanh(d0*diff)
//   yh = c0 + c1*t + c2*t^2 ; s = 0.5 + 0.5*tanh(yh); h = x_t + s*diff

#define SEQ   512
#define BLOCK 64
#define PITCH 36            // floats per thread in smem: 32 data + 4 pad
#define NCHUNK (SEQ / 16)   // 32

__device__ __forceinline__ float tanh_fast(float x) {
    float y;
    asm("tanh.approx.f32 %0, %1;" : "=f"(y) : "f"(x));
    return y;
}

__global__ void __launch_bounds__(BLOCK) rnn_scan_kernel(
    const float* __restrict__ X,
    const float* __restrict__ W1,
    const float* __restrict__ W2,
    const float* __restrict__ bias,
    const float* __restrict__ Wz,
    const float* __restrict__ Ws,
    float* __restrict__ out)
{
    __shared__ float sbuf[BLOCK * PITCH];

    const int lt = threadIdx.x;
    const int r  = blockIdx.x * BLOCK + lt;

    // ----- uniform scalar constants -----
    const float a1 = 1.0f / (1.0f + expf(W1[1] - W1[0]));
    const float a2 = 1.0f / (1.0f + expf(W2[1] - W2[0]));
    const float d0 = a1 - a2;
    const float wz = Wz[0];
    const float ws = Ws[0];
    const float b  = bias[0];
    const float c0 = 0.5f * (b + wz);
    const float c1 = 0.5f * ws;
    const float c2 = -wz;

    const float* row = X + (size_t)r * SEQ;
    float* my = sbuf + lt * PITCH;           // halves: [0..15] = A, [16..31] = B

    uint32_t sb;
    {
        uint64_t tmp;
        asm("cvta.to.shared.u64 %0, %1;" : "=l"(tmp) : "l"(my));
        sb = (uint32_t)tmp;
    }

    // issue one 16-float chunk (4 x 16B cp.async) into half (0=A, 1=B)
#define ISSUE(half, c) do {                                                  \
        _Pragma("unroll")                                                    \
        for (int j = 0; j < 4; ++j) {                                        \
            asm volatile("cp.async.cg.shared.global [%0], [%1], 16;"         \
                         :: "r"(sb + (unsigned)(((half) * 16 + j * 4) * 4)), \
                            "l"(row + (c) * 16 + j * 4) : "memory");         \
        }                                                                    \
        asm volatile("cp.async.commit_group;" ::: "memory");                 \
    } while (0)

#define WAIT1() asm volatile("cp.async.wait_group 1;" ::: "memory")
#define WAIT0() asm volatile("cp.async.wait_group 0;" ::: "memory")

    float h;

#define STEP(XT) do {                                         \
        float diff = h - (XT);                                \
        float tt   = tanh_fast(d0 * diff);                    \
        float yh   = fmaf(fmaf(c2, tt, c1), tt, c0);          \
        float s    = fmaf(0.5f, tanh_fast(yh), 0.5f);         \
        h          = fmaf(s, diff, (XT));                     \
    } while (0)

    // run 16 steps from smem half (E0 = first element index to process)
#define PROC(half, E0) do {                                                 \
        _Pragma("unroll")                                                   \
        for (int q = 0; q < 4; ++q) {                                       \
            float4 v = *reinterpret_cast<const float4*>(my + (half) * 16 + q * 4); \
            if (q > 0 || (E0) <= 0) STEP(v.x);                              \
            if (q > 0 || (E0) <= 1) STEP(v.y);                              \
            if (q > 0 || (E0) <= 2) STEP(v.z);                              \
            STEP(v.w);                                                      \
        }                                                                   \
    } while (0)

    // prologue: chunk0 -> A, chunk1 -> B
    ISSUE(0, 0);
    ISSUE(1, 1);

    WAIT1();                      // chunk 0 resident
    h = my[0];                    // h0 = X[:, 0]
    PROC(0, 1);                   // chunk 0, skip element 0

    // chunks 1..30
    #pragma unroll 1
    for (int c = 2; c < NCHUNK; c += 2) {
        ISSUE(0, c);              // prefetch chunk c -> A
        WAIT1();                  // chunk c-1 (B) resident
        PROC(1, 0);               // process chunk c-1
        ISSUE(1, c + 1);          // prefetch chunk c+1 -> B  (max c+1 = 31)
        WAIT1();                  // chunk c (A) resident
        PROC(0, 0);               // process chunk c
    }

    // final chunk 31 (in B)
    WAIT0();
    PROC(1, 0);

    out[r] = h;
}

extern "C" void kernel_launch(void* const* d_in, const int* in_sizes, int n_in,
                              void* d_out, int out_size)
{
    const float* X    = (const float*)d_in[0];
    const float* W1   = (const float*)d_in[1];
    const float* W2   = (const float*)d_in[2];
    const float* bias = (const float*)d_in[3];
    const float* Wz   = (const float*)d_in[4];
    const float* Ws   = (const float*)d_in[5];
    float* out = (float*)d_out;

    const int batch = out_size;                    // 65536
    const int grid  = (batch + BLOCK - 1) / BLOCK; // 1024
    rnn_scan_kernel<<<grid, BLOCK>>>(X, W1, W2, bias, Wz, Ws, out);
}